// round 10
// baseline (speedup 1.0000x reference)
#include <cuda_runtime.h>
#include <cuda_bf16.h>

// LightGCN 3-layer propagation. CSR (dst-sorted), atomic-free reduction.
// R4 inner loop preserved exactly. Changes vs R9:
//  - concat copy uw||iw -> g_emb (fused with detect + cnt zero) => all props
//    use the branch-free single-pointer gather.
//  - CSR stores {src, rs[src]}; prop scales the finished row by rs[dst] once;
//    fill loses both random cnt reads.

#define NUM_USERS 100000
#define NUM_ITEMS 50000
#define NN        150000
#define DIM       64
#define EDGES     1250000

#define NQ  (NN * 16)          // float4 count of one embedding buffer
#define UQ  (NUM_USERS * 16)

#define SCAN_B 256
#define NBLK   ((NN + SCAN_B - 1) / SCAN_B)   // 586
#define OFFSZ  (NBLK * SCAN_B)                // padded offset array size

// Device-global scratch. emb/A/B = 115MB, edges 10MB, rank 5MB.
__device__ float g_emb [NN * DIM];  // uw || iw
__device__ float g_bufA[NN * DIM];
__device__ float g_bufB[NN * DIM];
__device__ int   g_cnt [NN];        // in-degree (zeroed by scan1 after read)
__device__ float g_rs  [NN];        // rs[x] = deg>0 ? rsqrt(deg) : 0
__device__ int   g_rank[EDGES];     // per-edge arrival rank within its dst
__device__ int   g_off [OFFSZ + 1]; // block-LOCAL exclusive prefix of cnt
__device__ int   g_bsum[NBLK];      // exclusive block sums
__device__ int2  g_edge[EDGES];     // {src, __float_as_int(rs[src])} sorted by dst
__device__ int   g_is32;            // edge_index dtype flag

// ---------------------------------------------------------------------------
// Kernel 1: concat copy uw||iw -> g_emb (coalesced, full DRAM BW),
// zero g_cnt, detect dtype (block 0).
// ---------------------------------------------------------------------------
__global__ void copy_detect_kernel(const void* edge,
                                   const float* __restrict__ uw,
                                   const float* __restrict__ iw) {
    int i = blockIdx.x * blockDim.x + threadIdx.x;
    if (i < NQ) {
        ((float4*)g_emb)[i] = (i < UQ) ? ((const float4*)uw)[i]
                                       : ((const float4*)iw)[i - UQ];
    }
    if (i < NN) g_cnt[i] = 0;
    if (blockIdx.x == 0) {
        __shared__ int flag;
        if (threadIdx.x == 0) flag = 0;
        __syncthreads();
        long long v = ((const long long*)edge)[threadIdx.x * 4];
        if (v < 0 || v >= (long long)NN) atomicOr(&flag, 1);
        __syncthreads();
        if (threadIdx.x == 0) g_is32 = flag;
    }
}

__device__ __forceinline__ void load_edge(const void* edge, int e, int& s, int& d) {
    if (g_is32) {
        const int* ei = (const int*)edge;
        s = ei[e];
        d = ei[EDGES + e];
    } else {
        const long long* ei = (const long long*)edge;
        s = (int)ei[e];
        d = (int)ei[EDGES + e];
    }
}

// ---------------------------------------------------------------------------
// histogram + per-edge rank (atomicAdd return value)
// ---------------------------------------------------------------------------
__global__ void histrank_kernel(const void* edge) {
    int e = blockIdx.x * blockDim.x + threadIdx.x;
    if (e >= EDGES) return;
    int d;
    if (g_is32) d = ((const int*)edge)[EDGES + e];
    else        d = (int)((const long long*)edge)[EDGES + e];
    g_rank[e] = atomicAdd(&g_cnt[d], 1);
}

// ---------------------------------------------------------------------------
// shuffle-based scan; scan1 also emits rs[] and zeroes cnt (last reader).
// ---------------------------------------------------------------------------
__device__ __forceinline__ int warp_incl_scan(int v, int lid) {
    #pragma unroll
    for (int o = 1; o < 32; o <<= 1) {
        int t = __shfl_up_sync(0xffffffffu, v, o);
        if (lid >= o) v += t;
    }
    return v;
}

__global__ void scan1_kernel() {
    __shared__ int wsum[8];
    int i = blockIdx.x * SCAN_B + threadIdx.x;
    int v = (i < NN) ? g_cnt[i] : 0;
    if (i < NN) {
        g_rs[i]  = (v > 0) ? rsqrtf((float)v) : 0.f;
        g_cnt[i] = 0;                                  // reset for next replay
    }
    int wid = threadIdx.x >> 5, lid = threadIdx.x & 31;
    int incl = warp_incl_scan(v, lid);
    if (lid == 31) wsum[wid] = incl;
    __syncthreads();
    if (wid == 0) {
        int s = (lid < 8) ? wsum[lid] : 0;
        #pragma unroll
        for (int o = 1; o < 8; o <<= 1) {
            int t = __shfl_up_sync(0xffffffffu, s, o);
            if (lid >= o) s += t;
        }
        if (lid < 8) wsum[lid] = s;
    }
    __syncthreads();
    int base = (wid > 0) ? wsum[wid - 1] : 0;
    g_off[i] = base + incl - v;                       // block-local exclusive
    if (threadIdx.x == SCAN_B - 1) g_bsum[blockIdx.x] = base + incl;
    if (i == 0) g_off[OFFSZ] = 0;                     // padding guard
}

__global__ void scan2_kernel() {   // 1 block, NBLK=586 elements, 640 threads
    __shared__ int wsum[20];
    int i = threadIdx.x;
    int lid = i & 31, wid = i >> 5;
    int v = (i < NBLK) ? g_bsum[i] : 0;
    int incl = warp_incl_scan(v, lid);
    if (lid == 31) wsum[wid] = incl;
    __syncthreads();
    if (wid == 0) {
        int s = (lid < 20) ? wsum[lid] : 0;
        #pragma unroll
        for (int o = 1; o < 32; o <<= 1) {
            int t = __shfl_up_sync(0xffffffffu, s, o);
            if (lid >= o) s += t;
        }
        if (lid < 20) wsum[lid] = s;
    }
    __syncthreads();
    int base = (wid > 0) ? wsum[wid - 1] : 0;
    if (i < NBLK) g_bsum[i] = base + incl - v;        // exclusive block prefix
}

// ---------------------------------------------------------------------------
// CSR fill: pos = local_off[d] + bsum[d>>8] + rank[e].
// Stores {src, rs[src]} — one random read (rs[s]), no cnt reads.
// ---------------------------------------------------------------------------
__global__ void fill_kernel(const void* edge) {
    int e = blockIdx.x * blockDim.x + threadIdx.x;
    if (e >= EDGES) return;
    int s, d;
    load_edge(edge, e, s, d);
    float w = g_rs[s];
    int pos = g_off[d] + g_bsum[d >> 8] + g_rank[e];
    g_edge[pos] = make_int2(s, __float_as_int(w));
}

// ---------------------------------------------------------------------------
// Propagate (R4 inner loop, branch-free gather). 16 lanes per node;
// lane c owns float4 #c. Finished row scaled once by rs[n].
// MODE 0: nxt[n] = rs[n] * sum rs[s]*cur[s].
// MODE 1: final: out = (emb + c1 + cur_row + r)/4, duplicated.
// ---------------------------------------------------------------------------
template<int MODE>
__global__ void __launch_bounds__(256)
prop_kernel(const float* __restrict__ cur,
            const float* __restrict__ c1,
            float* __restrict__ nxt,
            float* __restrict__ out) {
    int t = blockIdx.x * blockDim.x + threadIdx.x;
    int n = t >> 4;
    int c = t & 15;
    if (n >= NN) return;
    int j   = g_off[n]     + g_bsum[n >> 8];
    int end = g_off[n + 1] + g_bsum[(n + 1) >> 8];
    float4 r = make_float4(0.f, 0.f, 0.f, 0.f);

    const int2* __restrict__ ge = g_edge;
    const float4* __restrict__ c4 = (const float4*)cur;
    for (; j + 4 <= end; j += 4) {
        int2 e0 = ge[j];
        int2 e1 = ge[j + 1];
        int2 e2 = ge[j + 2];
        int2 e3 = ge[j + 3];
        float4 v0 = c4[e0.x * 16 + c];
        float4 v1 = c4[e1.x * 16 + c];
        float4 v2 = c4[e2.x * 16 + c];
        float4 v3 = c4[e3.x * 16 + c];
        float w0 = __int_as_float(e0.y), w1 = __int_as_float(e1.y);
        float w2 = __int_as_float(e2.y), w3 = __int_as_float(e3.y);
        r.x += v0.x * w0 + v1.x * w1 + v2.x * w2 + v3.x * w3;
        r.y += v0.y * w0 + v1.y * w1 + v2.y * w2 + v3.y * w3;
        r.z += v0.z * w0 + v1.z * w1 + v2.z * w2 + v3.z * w3;
        r.w += v0.w * w0 + v1.w * w1 + v2.w * w2 + v3.w * w3;
    }
    #pragma unroll 1
    for (; j < end; ++j) {
        int2 e0 = ge[j];
        float w0 = __int_as_float(e0.y);
        float4 v0 = c4[e0.x * 16 + c];
        r.x += v0.x * w0; r.y += v0.y * w0; r.z += v0.z * w0; r.w += v0.w * w0;
    }

    float wn = g_rs[n];                    // rs[dst], broadcast across lanes
    r.x *= wn; r.y *= wn; r.z *= wn; r.w *= wn;

    int idx = n * 16 + c;
    if (MODE == 1) {
        float4 e = ((const float4*)g_emb)[idx];
        float4 a = ((const float4*)c1)[idx];   // layer-1 result
        float4 b = c4[idx];                    // layer-2 result
        float4 o;
        o.x = (e.x + a.x + b.x + r.x) * 0.25f;
        o.y = (e.y + a.y + b.y + r.y) * 0.25f;
        o.z = (e.z + a.z + b.z + r.z) * 0.25f;
        o.w = (e.w + a.w + b.w + r.w) * 0.25f;
        float4* op = (float4*)out;
        op[idx]      = o;
        op[NQ + idx] = o;
    } else {
        ((float4*)nxt)[idx] = r;
    }
}

// ---------------------------------------------------------------------------
extern "C" void kernel_launch(void* const* d_in, const int* in_sizes, int n_in,
                              void* d_out, int out_size) {
    const void*  edge = d_in[0];
    const float* uw   = (const float*)d_in[1];
    const float* iw   = (const float*)d_in[2];
    float*       out  = (float*)d_out;

    float* A = nullptr;
    float* B = nullptr;
    float* E = nullptr;
    cudaGetSymbolAddress((void**)&A, g_bufA);
    cudaGetSymbolAddress((void**)&B, g_bufB);
    cudaGetSymbolAddress((void**)&E, g_emb);

    const int T = 256;
    const int grid_q = (NQ + T - 1) / T;
    const int grid_e = (EDGES + T - 1) / T;
    const int grid_p = (NN * 16 + T - 1) / T;

    copy_detect_kernel<<<grid_q, T>>>(edge, uw, iw);  // concat + zero + detect
    histrank_kernel<<<grid_e, T>>>(edge);
    scan1_kernel<<<NBLK, SCAN_B>>>();                 // + rs + cnt reset
    scan2_kernel<<<1, 640>>>();
    fill_kernel<<<grid_e, T>>>(edge);

    prop_kernel<0><<<grid_p, T>>>(E, nullptr, B, nullptr);  // layer 1: emb -> B
    prop_kernel<0><<<grid_p, T>>>(B, nullptr, A, nullptr);  // layer 2: B -> A
    prop_kernel<1><<<grid_p, T>>>(A, B, nullptr, out);      // layer 3 + finalize
}

// round 11
// speedup vs baseline: 1.2024x; 1.2024x over previous
#include <cuda_runtime.h>
#include <cuda_fp16.h>

// LightGCN 3-layer propagation. CSR (dst-sorted), atomic-free reduction.
// fp16 intermediate buffers (emb_h, c1_h, c2_h) halve the gather traffic;
// accumulation and final output stay fp32. R4-proven inner loop shape.

#define NUM_USERS 100000
#define NUM_ITEMS 50000
#define NN        150000
#define DIM       64
#define EDGES     1250000

#define NQ  (NN * 16)          // float4 count of one fp32 embedding buffer
#define UQ  (NUM_USERS * 16)

#define SCAN_B 256
#define NBLK   ((NN + SCAN_B - 1) / SCAN_B)   // 586
#define OFFSZ  (NBLK * SCAN_B)

// Device-global scratch. fp16 bufs 3x19.2MB, edges 10MB, rank 5MB.
__device__ uint2 g_embh[NN * 16];   // uw||iw in fp16 (row = 16 uint2 = 64 halves)
__device__ uint2 g_c1h [NN * 16];   // layer-1 result, fp16
__device__ uint2 g_c2h [NN * 16];   // layer-2 result, fp16
__device__ int   g_cnt [NN];        // in-degree (zeroed by scan1 after read)
__device__ float g_rs  [NN];        // rs[x] = deg>0 ? rsqrt(deg) : 0
__device__ int   g_rank[EDGES];     // per-edge arrival rank within its dst
__device__ int   g_off [OFFSZ + 1]; // block-LOCAL exclusive prefix of cnt
__device__ int   g_bsum[NBLK];      // exclusive block sums
__device__ int2  g_edge[EDGES];     // {src, __float_as_int(rs[src])} sorted by dst
__device__ int   g_is32;            // edge_index dtype flag

// ---------------------------------------------------------------------------
// Kernel 1: fp16 concat uw||iw -> g_embh, zero g_cnt, detect dtype (block 0).
// ---------------------------------------------------------------------------
__global__ void copy_detect_kernel(const void* edge,
                                   const float* __restrict__ uw,
                                   const float* __restrict__ iw) {
    int i = blockIdx.x * blockDim.x + threadIdx.x;
    if (i < NQ) {
        float4 v = (i < UQ) ? ((const float4*)uw)[i]
                            : ((const float4*)iw)[i - UQ];
        __half2 p0 = __floats2half2_rn(v.x, v.y);
        __half2 p1 = __floats2half2_rn(v.z, v.w);
        g_embh[i] = make_uint2(*reinterpret_cast<unsigned*>(&p0),
                               *reinterpret_cast<unsigned*>(&p1));
    }
    if (i < NN) g_cnt[i] = 0;
    if (blockIdx.x == 0) {
        __shared__ int flag;
        if (threadIdx.x == 0) flag = 0;
        __syncthreads();
        long long v = ((const long long*)edge)[threadIdx.x * 4];
        if (v < 0 || v >= (long long)NN) atomicOr(&flag, 1);
        __syncthreads();
        if (threadIdx.x == 0) g_is32 = flag;
    }
}

__device__ __forceinline__ void load_edge(const void* edge, int e, int& s, int& d) {
    if (g_is32) {
        const int* ei = (const int*)edge;
        s = ei[e];
        d = ei[EDGES + e];
    } else {
        const long long* ei = (const long long*)edge;
        s = (int)ei[e];
        d = (int)ei[EDGES + e];
    }
}

// ---------------------------------------------------------------------------
// histogram + per-edge rank (atomicAdd return value)
// ---------------------------------------------------------------------------
__global__ void histrank_kernel(const void* edge) {
    int e = blockIdx.x * blockDim.x + threadIdx.x;
    if (e >= EDGES) return;
    int d;
    if (g_is32) d = ((const int*)edge)[EDGES + e];
    else        d = (int)((const long long*)edge)[EDGES + e];
    g_rank[e] = atomicAdd(&g_cnt[d], 1);
}

// ---------------------------------------------------------------------------
// shuffle-based scan; scan1 also emits rs[] and zeroes cnt (last reader).
// ---------------------------------------------------------------------------
__device__ __forceinline__ int warp_incl_scan(int v, int lid) {
    #pragma unroll
    for (int o = 1; o < 32; o <<= 1) {
        int t = __shfl_up_sync(0xffffffffu, v, o);
        if (lid >= o) v += t;
    }
    return v;
}

__global__ void scan1_kernel() {
    __shared__ int wsum[8];
    int i = blockIdx.x * SCAN_B + threadIdx.x;
    int v = (i < NN) ? g_cnt[i] : 0;
    if (i < NN) {
        g_rs[i]  = (v > 0) ? rsqrtf((float)v) : 0.f;
        g_cnt[i] = 0;                                  // reset for next replay
    }
    int wid = threadIdx.x >> 5, lid = threadIdx.x & 31;
    int incl = warp_incl_scan(v, lid);
    if (lid == 31) wsum[wid] = incl;
    __syncthreads();
    if (wid == 0) {
        int s = (lid < 8) ? wsum[lid] : 0;
        #pragma unroll
        for (int o = 1; o < 8; o <<= 1) {
            int t = __shfl_up_sync(0xffffffffu, s, o);
            if (lid >= o) s += t;
        }
        if (lid < 8) wsum[lid] = s;
    }
    __syncthreads();
    int base = (wid > 0) ? wsum[wid - 1] : 0;
    g_off[i] = base + incl - v;                       // block-local exclusive
    if (threadIdx.x == SCAN_B - 1) g_bsum[blockIdx.x] = base + incl;
    if (i == 0) g_off[OFFSZ] = 0;
}

__global__ void scan2_kernel() {   // 1 block, NBLK=586 elements, 640 threads
    __shared__ int wsum[20];
    int i = threadIdx.x;
    int lid = i & 31, wid = i >> 5;
    int v = (i < NBLK) ? g_bsum[i] : 0;
    int incl = warp_incl_scan(v, lid);
    if (lid == 31) wsum[wid] = incl;
    __syncthreads();
    if (wid == 0) {
        int s = (lid < 20) ? wsum[lid] : 0;
        #pragma unroll
        for (int o = 1; o < 32; o <<= 1) {
            int t = __shfl_up_sync(0xffffffffu, s, o);
            if (lid >= o) s += t;
        }
        if (lid < 20) wsum[lid] = s;
    }
    __syncthreads();
    int base = (wid > 0) ? wsum[wid - 1] : 0;
    if (i < NBLK) g_bsum[i] = base + incl - v;        // exclusive block prefix
}

// ---------------------------------------------------------------------------
// CSR fill: pos = local_off[d] + bsum[d>>8] + rank[e]; stores {src, rs[src]}.
// ---------------------------------------------------------------------------
__global__ void fill_kernel(const void* edge) {
    int e = blockIdx.x * blockDim.x + threadIdx.x;
    if (e >= EDGES) return;
    int s, d;
    load_edge(edge, e, s, d);
    float w = g_rs[s];
    int pos = g_off[d] + g_bsum[d >> 8] + g_rank[e];
    g_edge[pos] = make_int2(s, __float_as_int(w));
}

// ---------------------------------------------------------------------------
// Propagate. 16 lanes per node; lane c owns halves [4c..4c+3] (8B uint2).
// Gathers fp16, accumulates fp32, scales by rs[n], stores fp16 (MODE 0)
// or finalizes fp32 output (MODE 1).
// ---------------------------------------------------------------------------
__device__ __forceinline__ void acc_h(float4& r, uint2 v, float w) {
    float2 lo = __half22float2(*reinterpret_cast<const __half2*>(&v.x));
    float2 hi = __half22float2(*reinterpret_cast<const __half2*>(&v.y));
    r.x += lo.x * w; r.y += lo.y * w; r.z += hi.x * w; r.w += hi.y * w;
}

template<int MODE>
__global__ void __launch_bounds__(256)
prop_kernel(const uint2* __restrict__ cur,
            const float* __restrict__ uw,
            const float* __restrict__ iw,
            const uint2* __restrict__ c1,
            uint2* __restrict__ nxt,
            float* __restrict__ out) {
    int t = blockIdx.x * blockDim.x + threadIdx.x;
    int n = t >> 4;
    int c = t & 15;
    if (n >= NN) return;
    int j   = g_off[n]     + g_bsum[n >> 8];
    int end = g_off[n + 1] + g_bsum[(n + 1) >> 8];
    float4 r = make_float4(0.f, 0.f, 0.f, 0.f);

    const int2* __restrict__ ge = g_edge;
    for (; j + 4 <= end; j += 4) {
        int2 e0 = ge[j];
        int2 e1 = ge[j + 1];
        int2 e2 = ge[j + 2];
        int2 e3 = ge[j + 3];
        uint2 v0 = cur[e0.x * 16 + c];
        uint2 v1 = cur[e1.x * 16 + c];
        uint2 v2 = cur[e2.x * 16 + c];
        uint2 v3 = cur[e3.x * 16 + c];
        acc_h(r, v0, __int_as_float(e0.y));
        acc_h(r, v1, __int_as_float(e1.y));
        acc_h(r, v2, __int_as_float(e2.y));
        acc_h(r, v3, __int_as_float(e3.y));
    }
    #pragma unroll 1
    for (; j < end; ++j) {
        int2 e0 = ge[j];
        uint2 v0 = cur[e0.x * 16 + c];
        acc_h(r, v0, __int_as_float(e0.y));
    }

    float wn = g_rs[n];                    // rs[dst]
    r.x *= wn; r.y *= wn; r.z *= wn; r.w *= wn;

    int idx = n * 16 + c;
    if (MODE == 1) {
        // out = (emb_fp32 + c1 + c2 + r) / 4, duplicated
        float4 e = (n < NUM_USERS) ? ((const float4*)uw)[idx]
                                   : ((const float4*)iw)[idx - UQ];
        uint2 ua = c1[idx];                // layer-1 (fp16)
        uint2 ub = cur[idx];               // layer-2 (fp16)
        float2 a0 = __half22float2(*reinterpret_cast<const __half2*>(&ua.x));
        float2 a1 = __half22float2(*reinterpret_cast<const __half2*>(&ua.y));
        float2 b0 = __half22float2(*reinterpret_cast<const __half2*>(&ub.x));
        float2 b1 = __half22float2(*reinterpret_cast<const __half2*>(&ub.y));
        float4 o;
        o.x = (e.x + a0.x + b0.x + r.x) * 0.25f;
        o.y = (e.y + a0.y + b0.y + r.y) * 0.25f;
        o.z = (e.z + a1.x + b1.x + r.z) * 0.25f;
        o.w = (e.w + a1.y + b1.y + r.w) * 0.25f;
        float4* op = (float4*)out;
        op[idx]      = o;
        op[NQ + idx] = o;
    } else {
        __half2 p0 = __floats2half2_rn(r.x, r.y);
        __half2 p1 = __floats2half2_rn(r.z, r.w);
        nxt[idx] = make_uint2(*reinterpret_cast<unsigned*>(&p0),
                              *reinterpret_cast<unsigned*>(&p1));
    }
}

// ---------------------------------------------------------------------------
extern "C" void kernel_launch(void* const* d_in, const int* in_sizes, int n_in,
                              void* d_out, int out_size) {
    const void*  edge = d_in[0];
    const float* uw   = (const float*)d_in[1];
    const float* iw   = (const float*)d_in[2];
    float*       out  = (float*)d_out;

    uint2* E  = nullptr;
    uint2* C1 = nullptr;
    uint2* C2 = nullptr;
    cudaGetSymbolAddress((void**)&E,  g_embh);
    cudaGetSymbolAddress((void**)&C1, g_c1h);
    cudaGetSymbolAddress((void**)&C2, g_c2h);

    const int T = 256;
    const int grid_q = (NQ + T - 1) / T;
    const int grid_e = (EDGES + T - 1) / T;
    const int grid_p = (NN * 16 + T - 1) / T;

    copy_detect_kernel<<<grid_q, T>>>(edge, uw, iw);  // fp16 concat + zero + detect
    histrank_kernel<<<grid_e, T>>>(edge);
    scan1_kernel<<<NBLK, SCAN_B>>>();                 // + rs + cnt reset
    scan2_kernel<<<1, 640>>>();
    fill_kernel<<<grid_e, T>>>(edge);

    // layer 1: emb_h -> c1_h
    prop_kernel<0><<<grid_p, T>>>(E,  uw, iw, nullptr, C1, nullptr);
    // layer 2: c1_h -> c2_h
    prop_kernel<0><<<grid_p, T>>>(C1, uw, iw, nullptr, C2, nullptr);
    // layer 3: gather c2_h; finalize with emb(fp32) + c1_h + c2_h, duplicated
    prop_kernel<1><<<grid_p, T>>>(C2, uw, iw, C1, nullptr, out);
}

// round 12
// speedup vs baseline: 1.2482x; 1.0380x over previous
#include <cuda_runtime.h>
#include <cuda_fp16.h>

// LightGCN 3-layer propagation. CSR (dst-sorted), atomic-free reduction.
// fp16 intermediate buffers; props use 8 lanes/node with uint4 (16B) gathers
// to halve the per-edge warp-instruction count vs 16-lane uint2.

#define NUM_USERS 100000
#define NUM_ITEMS 50000
#define NN        150000
#define DIM       64
#define EDGES     1250000

#define NQ  (NN * 16)          // float4 count of one fp32 embedding buffer
#define UQ  (NUM_USERS * 16)

#define SCAN_B 256
#define NBLK   ((NN + SCAN_B - 1) / SCAN_B)   // 586
#define OFFSZ  (NBLK * SCAN_B)

// Device-global scratch. fp16 bufs 3x19.2MB, edges 10MB, rank 5MB.
__device__ uint4 g_embh[NN * 8];    // uw||iw fp16 (row = 8 uint4 = 64 halves)
__device__ uint4 g_c1h [NN * 8];    // layer-1 result, fp16
__device__ uint4 g_c2h [NN * 8];    // layer-2 result, fp16
__device__ int   g_cnt [NN];        // in-degree (zeroed by scan1 after read)
__device__ float g_rs  [NN];        // rs[x] = deg>0 ? rsqrt(deg) : 0
__device__ int   g_rank[EDGES];     // per-edge arrival rank within its dst
__device__ int   g_off [OFFSZ + 1]; // block-LOCAL exclusive prefix of cnt
__device__ int   g_bsum[NBLK];      // exclusive block sums
__device__ int2  g_edge[EDGES];     // {src, __float_as_int(rs[src])} sorted by dst
__device__ int   g_is32;            // edge_index dtype flag

// ---------------------------------------------------------------------------
// Kernel 1: fp16 concat uw||iw -> g_embh, zero g_cnt, detect dtype (block 0).
// ---------------------------------------------------------------------------
__global__ void copy_detect_kernel(const void* edge,
                                   const float* __restrict__ uw,
                                   const float* __restrict__ iw) {
    int i = blockIdx.x * blockDim.x + threadIdx.x;
    if (i < NQ) {
        float4 v = (i < UQ) ? ((const float4*)uw)[i]
                            : ((const float4*)iw)[i - UQ];
        __half2 p0 = __floats2half2_rn(v.x, v.y);
        __half2 p1 = __floats2half2_rn(v.z, v.w);
        ((uint2*)g_embh)[i] = make_uint2(*reinterpret_cast<unsigned*>(&p0),
                                         *reinterpret_cast<unsigned*>(&p1));
    }
    if (i < NN) g_cnt[i] = 0;
    if (blockIdx.x == 0) {
        __shared__ int flag;
        if (threadIdx.x == 0) flag = 0;
        __syncthreads();
        long long v = ((const long long*)edge)[threadIdx.x * 4];
        if (v < 0 || v >= (long long)NN) atomicOr(&flag, 1);
        __syncthreads();
        if (threadIdx.x == 0) g_is32 = flag;
    }
}

__device__ __forceinline__ void load_edge(const void* edge, int e, int& s, int& d) {
    if (g_is32) {
        const int* ei = (const int*)edge;
        s = ei[e];
        d = ei[EDGES + e];
    } else {
        const long long* ei = (const long long*)edge;
        s = (int)ei[e];
        d = (int)ei[EDGES + e];
    }
}

// ---------------------------------------------------------------------------
// histogram + per-edge rank (atomicAdd return value)
// ---------------------------------------------------------------------------
__global__ void histrank_kernel(const void* edge) {
    int e = blockIdx.x * blockDim.x + threadIdx.x;
    if (e >= EDGES) return;
    int d;
    if (g_is32) d = ((const int*)edge)[EDGES + e];
    else        d = (int)((const long long*)edge)[EDGES + e];
    g_rank[e] = atomicAdd(&g_cnt[d], 1);
}

// ---------------------------------------------------------------------------
// shuffle-based scan; scan1 also emits rs[] and zeroes cnt (last reader).
// ---------------------------------------------------------------------------
__device__ __forceinline__ int warp_incl_scan(int v, int lid) {
    #pragma unroll
    for (int o = 1; o < 32; o <<= 1) {
        int t = __shfl_up_sync(0xffffffffu, v, o);
        if (lid >= o) v += t;
    }
    return v;
}

__global__ void scan1_kernel() {
    __shared__ int wsum[8];
    int i = blockIdx.x * SCAN_B + threadIdx.x;
    int v = (i < NN) ? g_cnt[i] : 0;
    if (i < NN) {
        g_rs[i]  = (v > 0) ? rsqrtf((float)v) : 0.f;
        g_cnt[i] = 0;                                  // reset for next replay
    }
    int wid = threadIdx.x >> 5, lid = threadIdx.x & 31;
    int incl = warp_incl_scan(v, lid);
    if (lid == 31) wsum[wid] = incl;
    __syncthreads();
    if (wid == 0) {
        int s = (lid < 8) ? wsum[lid] : 0;
        #pragma unroll
        for (int o = 1; o < 8; o <<= 1) {
            int t = __shfl_up_sync(0xffffffffu, s, o);
            if (lid >= o) s += t;
        }
        if (lid < 8) wsum[lid] = s;
    }
    __syncthreads();
    int base = (wid > 0) ? wsum[wid - 1] : 0;
    g_off[i] = base + incl - v;                       // block-local exclusive
    if (threadIdx.x == SCAN_B - 1) g_bsum[blockIdx.x] = base + incl;
    if (i == 0) g_off[OFFSZ] = 0;
}

__global__ void scan2_kernel() {   // 1 block, NBLK=586 elements, 640 threads
    __shared__ int wsum[20];
    int i = threadIdx.x;
    int lid = i & 31, wid = i >> 5;
    int v = (i < NBLK) ? g_bsum[i] : 0;
    int incl = warp_incl_scan(v, lid);
    if (lid == 31) wsum[wid] = incl;
    __syncthreads();
    if (wid == 0) {
        int s = (lid < 20) ? wsum[lid] : 0;
        #pragma unroll
        for (int o = 1; o < 32; o <<= 1) {
            int t = __shfl_up_sync(0xffffffffu, s, o);
            if (lid >= o) s += t;
        }
        if (lid < 20) wsum[lid] = s;
    }
    __syncthreads();
    int base = (wid > 0) ? wsum[wid - 1] : 0;
    if (i < NBLK) g_bsum[i] = base + incl - v;        // exclusive block prefix
}

// ---------------------------------------------------------------------------
// CSR fill: pos = local_off[d] + bsum[d>>8] + rank[e]; stores {src, rs[src]}.
// ---------------------------------------------------------------------------
__global__ void fill_kernel(const void* edge) {
    int e = blockIdx.x * blockDim.x + threadIdx.x;
    if (e >= EDGES) return;
    int s, d;
    load_edge(edge, e, s, d);
    float w = g_rs[s];
    int pos = g_off[d] + g_bsum[d >> 8] + g_rank[e];
    g_edge[pos] = make_int2(s, __float_as_int(w));
}

// ---------------------------------------------------------------------------
// Propagate. 8 lanes per node; lane c owns halves [8c..8c+7] (16B uint4).
// Gathers fp16, accumulates fp32 (8 floats), scales by rs[n], stores fp16
// (MODE 0) or finalizes fp32 output (MODE 1).
// ---------------------------------------------------------------------------
__device__ __forceinline__ void acc_h8(float4& ra, float4& rb, uint4 v, float w) {
    float2 q0 = __half22float2(*reinterpret_cast<const __half2*>(&v.x));
    float2 q1 = __half22float2(*reinterpret_cast<const __half2*>(&v.y));
    float2 q2 = __half22float2(*reinterpret_cast<const __half2*>(&v.z));
    float2 q3 = __half22float2(*reinterpret_cast<const __half2*>(&v.w));
    ra.x += q0.x * w; ra.y += q0.y * w; ra.z += q1.x * w; ra.w += q1.y * w;
    rb.x += q2.x * w; rb.y += q2.y * w; rb.z += q3.x * w; rb.w += q3.y * w;
}

template<int MODE>
__global__ void __launch_bounds__(256)
prop_kernel(const uint4* __restrict__ cur,
            const float* __restrict__ uw,
            const float* __restrict__ iw,
            const uint4* __restrict__ c1,
            uint4* __restrict__ nxt,
            float* __restrict__ out) {
    int t = blockIdx.x * blockDim.x + threadIdx.x;
    int n = t >> 3;
    int c = t & 7;
    if (n >= NN) return;
    int j   = g_off[n]     + g_bsum[n >> 8];
    int end = g_off[n + 1] + g_bsum[(n + 1) >> 8];
    float4 ra = make_float4(0.f, 0.f, 0.f, 0.f);
    float4 rb = make_float4(0.f, 0.f, 0.f, 0.f);

    const int2* __restrict__ ge = g_edge;
    for (; j + 4 <= end; j += 4) {
        int2 e0 = ge[j];
        int2 e1 = ge[j + 1];
        int2 e2 = ge[j + 2];
        int2 e3 = ge[j + 3];
        uint4 v0 = cur[e0.x * 8 + c];
        uint4 v1 = cur[e1.x * 8 + c];
        uint4 v2 = cur[e2.x * 8 + c];
        uint4 v3 = cur[e3.x * 8 + c];
        acc_h8(ra, rb, v0, __int_as_float(e0.y));
        acc_h8(ra, rb, v1, __int_as_float(e1.y));
        acc_h8(ra, rb, v2, __int_as_float(e2.y));
        acc_h8(ra, rb, v3, __int_as_float(e3.y));
    }
    #pragma unroll 1
    for (; j < end; ++j) {
        int2 e0 = ge[j];
        uint4 v0 = cur[e0.x * 8 + c];
        acc_h8(ra, rb, v0, __int_as_float(e0.y));
    }

    float wn = g_rs[n];                    // rs[dst]
    ra.x *= wn; ra.y *= wn; ra.z *= wn; ra.w *= wn;
    rb.x *= wn; rb.y *= wn; rb.z *= wn; rb.w *= wn;

    if (MODE == 1) {
        // out = (emb_fp32 + c1 + c2 + r)/4, duplicated.
        // Lane owns float4 slots (n*16 + 2c) and (n*16 + 2c + 1).
        int fo = n * 16 + c * 2;
        const float4* ew = (n < NUM_USERS) ? (const float4*)uw
                                           : (const float4*)iw - UQ;
        float4 ea = ew[fo];
        float4 eb = ew[fo + 1];
        uint4 uc1 = c1[n * 8 + c];         // layer-1 (fp16)
        uint4 uc2 = cur[n * 8 + c];        // layer-2 (fp16)
        float4 za = make_float4(0.f, 0.f, 0.f, 0.f);
        float4 zb = make_float4(0.f, 0.f, 0.f, 0.f);
        acc_h8(za, zb, uc1, 1.0f);
        acc_h8(za, zb, uc2, 1.0f);
        float4 oa, ob;
        oa.x = (ea.x + za.x + ra.x) * 0.25f;
        oa.y = (ea.y + za.y + ra.y) * 0.25f;
        oa.z = (ea.z + za.z + ra.z) * 0.25f;
        oa.w = (ea.w + za.w + ra.w) * 0.25f;
        ob.x = (eb.x + zb.x + rb.x) * 0.25f;
        ob.y = (eb.y + zb.y + rb.y) * 0.25f;
        ob.z = (eb.z + zb.z + rb.z) * 0.25f;
        ob.w = (eb.w + zb.w + rb.w) * 0.25f;
        float4* op = (float4*)out;
        op[fo]          = oa;
        op[fo + 1]      = ob;
        op[NQ + fo]     = oa;
        op[NQ + fo + 1] = ob;
    } else {
        __half2 p0 = __floats2half2_rn(ra.x, ra.y);
        __half2 p1 = __floats2half2_rn(ra.z, ra.w);
        __half2 p2 = __floats2half2_rn(rb.x, rb.y);
        __half2 p3 = __floats2half2_rn(rb.z, rb.w);
        nxt[n * 8 + c] = make_uint4(*reinterpret_cast<unsigned*>(&p0),
                                    *reinterpret_cast<unsigned*>(&p1),
                                    *reinterpret_cast<unsigned*>(&p2),
                                    *reinterpret_cast<unsigned*>(&p3));
    }
}

// ---------------------------------------------------------------------------
extern "C" void kernel_launch(void* const* d_in, const int* in_sizes, int n_in,
                              void* d_out, int out_size) {
    const void*  edge = d_in[0];
    const float* uw   = (const float*)d_in[1];
    const float* iw   = (const float*)d_in[2];
    float*       out  = (float*)d_out;

    uint4* E  = nullptr;
    uint4* C1 = nullptr;
    uint4* C2 = nullptr;
    cudaGetSymbolAddress((void**)&E,  g_embh);
    cudaGetSymbolAddress((void**)&C1, g_c1h);
    cudaGetSymbolAddress((void**)&C2, g_c2h);

    const int T = 256;
    const int grid_q = (NQ + T - 1) / T;
    const int grid_e = (EDGES + T - 1) / T;
    const int grid_p = (NN * 8 + T - 1) / T;   // 8 lanes/node

    copy_detect_kernel<<<grid_q, T>>>(edge, uw, iw);  // fp16 concat + zero + detect
    histrank_kernel<<<grid_e, T>>>(edge);
    scan1_kernel<<<NBLK, SCAN_B>>>();                 // + rs + cnt reset
    scan2_kernel<<<1, 640>>>();
    fill_kernel<<<grid_e, T>>>(edge);

    // layer 1: emb_h -> c1_h
    prop_kernel<0><<<grid_p, T>>>(E,  uw, iw, nullptr, C1, nullptr);
    // layer 2: c1_h -> c2_h
    prop_kernel<0><<<grid_p, T>>>(C1, uw, iw, nullptr, C2, nullptr);
    // layer 3: gather c2_h; finalize with emb(fp32) + c1_h + c2_h, duplicated
    prop_kernel<1><<<grid_p, T>>>(C2, uw, iw, C1, nullptr, out);
}

// round 13
// speedup vs baseline: 1.2935x; 1.0363x over previous
#include <cuda_runtime.h>
#include <cuda_fp16.h>

// LightGCN 3-layer propagation. CSR (dst-sorted), atomic-free reduction.
// fp16 intermediates, 8-lane uint4 props (R12 structure, untouched).
// Preprocessing = 3 launches: histrank(+fp16 concat) -> scan(1+2 fused via
// last-block-done) -> fill.

#define NUM_USERS 100000
#define NUM_ITEMS 50000
#define NN        150000
#define DIM       64
#define EDGES     1250000

#define NQ  (NN * 16)          // float4 count of one fp32 embedding buffer
#define UQ  (NUM_USERS * 16)

#define SCAN_B 256
#define NBLK   ((NN + SCAN_B - 1) / SCAN_B)   // 586
#define OFFSZ  (NBLK * SCAN_B)

// Device-global scratch. fp16 bufs 3x19.2MB, edges 10MB, rank 5MB.
__device__ uint4 g_embh[NN * 8];    // uw||iw fp16 (row = 8 uint4 = 64 halves)
__device__ uint4 g_c1h [NN * 8];    // layer-1 result, fp16
__device__ uint4 g_c2h [NN * 8];    // layer-2 result, fp16
__device__ int   g_cnt [NN];        // in-degree (zeroed by scan after read)
__device__ float g_rs  [NN];        // rs[x] = deg>0 ? rsqrt(deg) : 0
__device__ int   g_rank[EDGES];     // per-edge arrival rank within its dst
__device__ int   g_off [OFFSZ + 1]; // block-LOCAL exclusive prefix of cnt
__device__ int   g_bsum[NBLK];      // exclusive block sums
__device__ int2  g_edge[EDGES];     // {src, __float_as_int(rs[src])} sorted by dst
__device__ int   g_done;            // last-block-done counter (self-resetting)

// ---------------------------------------------------------------------------
// Per-warp dtype detection: all warps sample the SAME first 8 int64 slots
// (one cache line) -> consistent verdict chip-wide.
// ---------------------------------------------------------------------------
__device__ __forceinline__ bool detect_is32(const void* edge) {
    int lid = threadIdx.x & 31;
    bool bad = false;
    if (lid < 8) {
        long long v = ((const long long*)edge)[lid];
        bad = (v < 0 || v >= (long long)NN);
    }
    return __ballot_sync(0xffffffffu, bad) != 0;
}

// ---------------------------------------------------------------------------
// histogram + per-edge rank; grid-stride fp16 concat uw||iw -> g_embh rides
// in the atomic latency shadow.
// ---------------------------------------------------------------------------
__global__ void histrank_kernel(const void* edge,
                                const float* __restrict__ uw,
                                const float* __restrict__ iw) {
    int t = blockIdx.x * blockDim.x + threadIdx.x;
    int stride = gridDim.x * blockDim.x;
    bool is32 = detect_is32(edge);

    // fp16 concat: NQ = 2.4M uint2 over 1.25M threads (2 iters)
    uint2* eh = (uint2*)g_embh;
    for (int i = t; i < NQ; i += stride) {
        float4 v = (i < UQ) ? ((const float4*)uw)[i]
                            : ((const float4*)iw)[i - UQ];
        __half2 p0 = __floats2half2_rn(v.x, v.y);
        __half2 p1 = __floats2half2_rn(v.z, v.w);
        eh[i] = make_uint2(*reinterpret_cast<unsigned*>(&p0),
                           *reinterpret_cast<unsigned*>(&p1));
    }

    if (t >= EDGES) return;
    int d;
    if (is32) d = ((const int*)edge)[EDGES + t];
    else      d = (int)((const long long*)edge)[EDGES + t];
    g_rank[t] = atomicAdd(&g_cnt[d], 1);
}

// ---------------------------------------------------------------------------
// Fused scan: per-block exclusive scan of cnt (+ rs emit + cnt reset), then
// the LAST block to finish scans the 586 block sums (no extra launch).
// ---------------------------------------------------------------------------
__device__ __forceinline__ int warp_incl_scan(int v, int lid) {
    #pragma unroll
    for (int o = 1; o < 32; o <<= 1) {
        int t = __shfl_up_sync(0xffffffffu, v, o);
        if (lid >= o) v += t;
    }
    return v;
}

__global__ void __launch_bounds__(SCAN_B)
scan_kernel() {
    __shared__ int wsum[8];
    __shared__ int s_last;
    int b = blockIdx.x;
    int i = b * SCAN_B + threadIdx.x;
    int v = (i < NN) ? g_cnt[i] : 0;
    if (i < NN) {
        g_rs[i]  = (v > 0) ? rsqrtf((float)v) : 0.f;
        g_cnt[i] = 0;                                  // reset for next replay
    }
    int wid = threadIdx.x >> 5, lid = threadIdx.x & 31;
    int incl = warp_incl_scan(v, lid);
    if (lid == 31) wsum[wid] = incl;
    __syncthreads();
    if (wid == 0) {
        int s = (lid < 8) ? wsum[lid] : 0;
        #pragma unroll
        for (int o = 1; o < 8; o <<= 1) {
            int t = __shfl_up_sync(0xffffffffu, s, o);
            if (lid >= o) s += t;
        }
        if (lid < 8) wsum[lid] = s;
    }
    __syncthreads();
    int base = (wid > 0) ? wsum[wid - 1] : 0;
    g_off[i] = base + incl - v;                        // block-local exclusive
    if (threadIdx.x == SCAN_B - 1) g_bsum[b] = base + incl;
    if (i == 0) g_off[OFFSZ] = 0;

    // ---- last-block-done: the final block scans g_bsum in place ----
    __threadfence();
    if (threadIdx.x == 0) {
        int done = atomicAdd(&g_done, 1);
        s_last = (done == (int)gridDim.x - 1) ? 1 : 0;
    }
    __syncthreads();
    if (!s_last) return;

    // exclusive scan of g_bsum[0..NBLK): thread t owns [3t, 3t+3)
    __shared__ int wsum2[8];
    int b3 = threadIdx.x * 3;
    int a0 = (b3     < NBLK) ? g_bsum[b3]     : 0;
    int a1 = (b3 + 1 < NBLK) ? g_bsum[b3 + 1] : 0;
    int a2 = (b3 + 2 < NBLK) ? g_bsum[b3 + 2] : 0;
    int tsum = a0 + a1 + a2;
    int incl2 = warp_incl_scan(tsum, lid);
    if (lid == 31) wsum2[wid] = incl2;
    __syncthreads();
    if (wid == 0) {
        int s = (lid < 8) ? wsum2[lid] : 0;
        #pragma unroll
        for (int o = 1; o < 8; o <<= 1) {
            int t = __shfl_up_sync(0xffffffffu, s, o);
            if (lid >= o) s += t;
        }
        if (lid < 8) wsum2[lid] = s;
    }
    __syncthreads();
    int tbase = ((wid > 0) ? wsum2[wid - 1] : 0) + incl2 - tsum;
    if (b3     < NBLK) g_bsum[b3]     = tbase;
    if (b3 + 1 < NBLK) g_bsum[b3 + 1] = tbase + a0;
    if (b3 + 2 < NBLK) g_bsum[b3 + 2] = tbase + a0 + a1;
    if (threadIdx.x == 0) g_done = 0;                  // reset for next replay
}

// ---------------------------------------------------------------------------
// CSR fill: pos = local_off[d] + bsum[d>>8] + rank[e]; stores {src, rs[src]}.
// ---------------------------------------------------------------------------
__global__ void fill_kernel(const void* edge) {
    int e = blockIdx.x * blockDim.x + threadIdx.x;
    if (e >= EDGES) return;
    bool is32 = detect_is32(edge);
    int s, d;
    if (is32) {
        const int* ei = (const int*)edge;
        s = ei[e];
        d = ei[EDGES + e];
    } else {
        const long long* ei = (const long long*)edge;
        s = (int)ei[e];
        d = (int)ei[EDGES + e];
    }
    float w = g_rs[s];
    int pos = g_off[d] + g_bsum[d >> 8] + g_rank[e];
    g_edge[pos] = make_int2(s, __float_as_int(w));
}

// ---------------------------------------------------------------------------
// Propagate (R12 structure, untouched). 8 lanes per node; lane c owns halves
// [8c..8c+7] (16B uint4). fp16 gathers, fp32 accumulate, scale by rs[n].
// ---------------------------------------------------------------------------
__device__ __forceinline__ void acc_h8(float4& ra, float4& rb, uint4 v, float w) {
    float2 q0 = __half22float2(*reinterpret_cast<const __half2*>(&v.x));
    float2 q1 = __half22float2(*reinterpret_cast<const __half2*>(&v.y));
    float2 q2 = __half22float2(*reinterpret_cast<const __half2*>(&v.z));
    float2 q3 = __half22float2(*reinterpret_cast<const __half2*>(&v.w));
    ra.x += q0.x * w; ra.y += q0.y * w; ra.z += q1.x * w; ra.w += q1.y * w;
    rb.x += q2.x * w; rb.y += q2.y * w; rb.z += q3.x * w; rb.w += q3.y * w;
}

template<int MODE>
__global__ void __launch_bounds__(256)
prop_kernel(const uint4* __restrict__ cur,
            const float* __restrict__ uw,
            const float* __restrict__ iw,
            const uint4* __restrict__ c1,
            uint4* __restrict__ nxt,
            float* __restrict__ out) {
    int t = blockIdx.x * blockDim.x + threadIdx.x;
    int n = t >> 3;
    int c = t & 7;
    if (n >= NN) return;
    int j   = g_off[n]     + g_bsum[n >> 8];
    int end = g_off[n + 1] + g_bsum[(n + 1) >> 8];
    float4 ra = make_float4(0.f, 0.f, 0.f, 0.f);
    float4 rb = make_float4(0.f, 0.f, 0.f, 0.f);

    const int2* __restrict__ ge = g_edge;
    for (; j + 4 <= end; j += 4) {
        int2 e0 = ge[j];
        int2 e1 = ge[j + 1];
        int2 e2 = ge[j + 2];
        int2 e3 = ge[j + 3];
        uint4 v0 = cur[e0.x * 8 + c];
        uint4 v1 = cur[e1.x * 8 + c];
        uint4 v2 = cur[e2.x * 8 + c];
        uint4 v3 = cur[e3.x * 8 + c];
        acc_h8(ra, rb, v0, __int_as_float(e0.y));
        acc_h8(ra, rb, v1, __int_as_float(e1.y));
        acc_h8(ra, rb, v2, __int_as_float(e2.y));
        acc_h8(ra, rb, v3, __int_as_float(e3.y));
    }
    #pragma unroll 1
    for (; j < end; ++j) {
        int2 e0 = ge[j];
        uint4 v0 = cur[e0.x * 8 + c];
        acc_h8(ra, rb, v0, __int_as_float(e0.y));
    }

    float wn = g_rs[n];                    // rs[dst]
    ra.x *= wn; ra.y *= wn; ra.z *= wn; ra.w *= wn;
    rb.x *= wn; rb.y *= wn; rb.z *= wn; rb.w *= wn;

    if (MODE == 1) {
        int fo = n * 16 + c * 2;
        const float4* ew = (n < NUM_USERS) ? (const float4*)uw
                                           : (const float4*)iw - UQ;
        float4 ea = ew[fo];
        float4 eb = ew[fo + 1];
        uint4 uc1 = c1[n * 8 + c];         // layer-1 (fp16)
        uint4 uc2 = cur[n * 8 + c];        // layer-2 (fp16)
        float4 za = make_float4(0.f, 0.f, 0.f, 0.f);
        float4 zb = make_float4(0.f, 0.f, 0.f, 0.f);
        acc_h8(za, zb, uc1, 1.0f);
        acc_h8(za, zb, uc2, 1.0f);
        float4 oa, ob;
        oa.x = (ea.x + za.x + ra.x) * 0.25f;
        oa.y = (ea.y + za.y + ra.y) * 0.25f;
        oa.z = (ea.z + za.z + ra.z) * 0.25f;
        oa.w = (ea.w + za.w + ra.w) * 0.25f;
        ob.x = (eb.x + zb.x + rb.x) * 0.25f;
        ob.y = (eb.y + zb.y + rb.y) * 0.25f;
        ob.z = (eb.z + zb.z + rb.z) * 0.25f;
        ob.w = (eb.w + zb.w + rb.w) * 0.25f;
        float4* op = (float4*)out;
        op[fo]          = oa;
        op[fo + 1]      = ob;
        op[NQ + fo]     = oa;
        op[NQ + fo + 1] = ob;
    } else {
        __half2 p0 = __floats2half2_rn(ra.x, ra.y);
        __half2 p1 = __floats2half2_rn(ra.z, ra.w);
        __half2 p2 = __floats2half2_rn(rb.x, rb.y);
        __half2 p3 = __floats2half2_rn(rb.z, rb.w);
        nxt[n * 8 + c] = make_uint4(*reinterpret_cast<unsigned*>(&p0),
                                    *reinterpret_cast<unsigned*>(&p1),
                                    *reinterpret_cast<unsigned*>(&p2),
                                    *reinterpret_cast<unsigned*>(&p3));
    }
}

// ---------------------------------------------------------------------------
extern "C" void kernel_launch(void* const* d_in, const int* in_sizes, int n_in,
                              void* d_out, int out_size) {
    const void*  edge = d_in[0];
    const float* uw   = (const float*)d_in[1];
    const float* iw   = (const float*)d_in[2];
    float*       out  = (float*)d_out;

    uint4* E  = nullptr;
    uint4* C1 = nullptr;
    uint4* C2 = nullptr;
    cudaGetSymbolAddress((void**)&E,  g_embh);
    cudaGetSymbolAddress((void**)&C1, g_c1h);
    cudaGetSymbolAddress((void**)&C2, g_c2h);

    const int T = 256;
    const int grid_e = (EDGES + T - 1) / T;
    const int grid_p = (NN * 8 + T - 1) / T;   // 8 lanes/node

    histrank_kernel<<<grid_e, T>>>(edge, uw, iw);  // + fp16 concat
    scan_kernel<<<NBLK, SCAN_B>>>();               // scan1+scan2 fused
    fill_kernel<<<grid_e, T>>>(edge);

    // layer 1: emb_h -> c1_h
    prop_kernel<0><<<grid_p, T>>>(E,  uw, iw, nullptr, C1, nullptr);
    // layer 2: c1_h -> c2_h
    prop_kernel<0><<<grid_p, T>>>(C1, uw, iw, nullptr, C2, nullptr);
    // layer 3: gather c2_h; finalize with emb(fp32) + c1_h + c2_h, duplicated
    prop_kernel<1><<<grid_p, T>>>(C2, uw, iw, C1, nullptr, out);
}